// round 4
// baseline (speedup 1.0000x reference)
#include <cuda_runtime.h>
#include <cuda_fp16.h>
#include <cstdint>

#define N_NODES 50000
#define N_EDGES 800000
#define E_TOT   (N_EDGES + N_NODES)
#define D 128
#define H 4
#define NB ((N_NODES + 1023) / 1024)   // 49 scan blocks

// ---------------- scratch (static device globals; no allocs) ----------------
__device__ __align__(16) float  g_h  [N_NODES * D];
__device__ __align__(16) float  g_h2 [N_NODES * D];
__device__ __align__(16) __half g_xph[N_NODES * D];   // fp16 message mirror
__device__ __align__(16) float  g_als[N_NODES * H];
__device__ __align__(16) float  g_ald[N_NODES * H];
__device__ int g_deg[N_NODES];        // zero-initialized; re-zeroed by k_scan1
__device__ int g_rowptr[N_NODES + 1];
__device__ int g_wp[N_NODES];
__device__ int g_col[E_TOT];
__device__ int g_bsum[64];

// ---------------- CSR build (4 kernels) ----------------
// g_deg starts at 0 (static init on first call; k_scan1 re-zeroes each run).
__global__ void k_count(const int* __restrict__ ei) {
    int i = blockIdx.x * blockDim.x + threadIdx.x;
    if (i < N_EDGES) atomicAdd(&g_deg[ei[N_EDGES + i]], 1);
}

// block-wise exclusive scan of (deg+1); also consumes & re-zeroes deg.
__global__ void k_scan1() {
    __shared__ int sm[1024];
    int i = blockIdx.x * 1024 + threadIdx.x;
    int v = 0;
    if (i < N_NODES) {
        v = g_deg[i] + 1;          // +1 = self loop
        g_deg[i] = 0;              // leave clean state for next replay
    }
    sm[threadIdx.x] = v;
    __syncthreads();
    for (int off = 1; off < 1024; off <<= 1) {
        int t = (threadIdx.x >= off) ? sm[threadIdx.x - off] : 0;
        __syncthreads();
        sm[threadIdx.x] += t;
        __syncthreads();
    }
    if (i < N_NODES) g_rowptr[i] = sm[threadIdx.x] - v;   // exclusive in-block
    if (threadIdx.x == 1023) g_bsum[blockIdx.x] = sm[1023];
}

// apply block offsets; each block redundantly scans the 49 block sums.
__global__ void k_scan3() {
    __shared__ int sb[64];
    __shared__ int sb_ex[64];
    int t = threadIdx.x;
    if (t < 64) sb[t] = (t < NB) ? g_bsum[t] : 0;
    __syncthreads();
    for (int off = 1; off < 64; off <<= 1) {
        int x = (t < 64 && t >= off) ? sb[t - off] : 0;
        __syncthreads();
        if (t < 64) sb[t] += x;
        __syncthreads();
    }
    if (t < 64) sb_ex[t] = (t == 0) ? 0 : sb[t - 1];
    __syncthreads();
    int i = blockIdx.x * blockDim.x + t;
    if (i < N_NODES) {
        int r = g_rowptr[i] + sb_ex[i >> 10];
        g_rowptr[i] = r;
        g_wp[i] = r;
    }
    if (i == 0) g_rowptr[N_NODES] = E_TOT;
}

__global__ void k_scatter(const int* __restrict__ ei) {
    int i = blockIdx.x * blockDim.x + threadIdx.x;
    if (i < N_NODES) {
        int p = atomicAdd(&g_wp[i], 1);
        g_col[p] = i;                          // self loop
    } else if (i < N_NODES + N_EDGES) {
        int j = i - N_NODES;
        int s = ei[j], d = ei[N_EDGES + j];
        int p = atomicAdd(&g_wp[d], 1);
        g_col[p] = s;
    }
}

// ---------------- tf32 tensor-core GEMM ----------------
// C[N,128] = A[N,128] @ W[128,128], BM=128 BN=128 BK=32, 256 thr.
// asrc==null: fp32 (+bias) epilogue. asrc!=null: fp16 mirror + fused logits.
__device__ __forceinline__ uint32_t f2tf32(float f) {
    uint32_t r;
    asm("cvt.rna.tf32.f32 %0, %1;" : "=r"(r) : "f"(f));
    return r;
}

__global__ void __launch_bounds__(256) k_gemm_tc(
        const float* Aext, int asel,
        const float* __restrict__ W,
        const float* __restrict__ bias,
        int csel,
        const float* __restrict__ asrc,
        const float* __restrict__ adst) {
    __shared__ uint32_t As[128 * 36];   // [m][k], stride 36
    __shared__ uint32_t Bs[32 * 136];   // [k][n], stride 136

    const float* A = Aext ? Aext : (asel == 0 ? g_h : g_h2);
    float* Cp = (csel == 0 ? g_h : g_h2);

    const int bm = blockIdx.x * 128;
    const int tid = threadIdx.x;
    const int wid = tid >> 5, lane = tid & 31;
    const int g = lane >> 2, tig = lane & 3;
    const int wm = (wid & 3) * 32;
    const int wn = (wid >> 2) * 64;

    float acc[2][8][4];
#pragma unroll
    for (int mt = 0; mt < 2; mt++)
#pragma unroll
        for (int nt = 0; nt < 8; nt++)
#pragma unroll
            for (int q = 0; q < 4; q++) acc[mt][nt][q] = 0.f;

    for (int k0 = 0; k0 < 128; k0 += 32) {
#pragma unroll
        for (int it = 0; it < 4; it++) {
            int idx = tid + 256 * it;
            int row = idx >> 3, c4 = (idx & 7) << 2;
            float4 v = make_float4(0.f, 0.f, 0.f, 0.f);
            if (bm + row < N_NODES)
                v = *(const float4*)(A + (size_t)(bm + row) * D + k0 + c4);
            uint32_t* p = &As[row * 36 + c4];
            p[0] = f2tf32(v.x); p[1] = f2tf32(v.y);
            p[2] = f2tf32(v.z); p[3] = f2tf32(v.w);
        }
#pragma unroll
        for (int it = 0; it < 4; it++) {
            int idx = tid + 256 * it;
            int row = idx >> 5, c4 = (idx & 31) << 2;
            float4 v = *(const float4*)(W + (size_t)(k0 + row) * D + c4);
            uint32_t* p = &Bs[row * 136 + c4];
            p[0] = f2tf32(v.x); p[1] = f2tf32(v.y);
            p[2] = f2tf32(v.z); p[3] = f2tf32(v.w);
        }
        __syncthreads();

#pragma unroll
        for (int kk = 0; kk < 32; kk += 8) {
            uint32_t a[2][4], b[8][2];
#pragma unroll
            for (int mt = 0; mt < 2; mt++) {
                int r0 = wm + mt * 16 + g;
                a[mt][0] = As[r0 * 36 + kk + tig];
                a[mt][1] = As[(r0 + 8) * 36 + kk + tig];
                a[mt][2] = As[r0 * 36 + kk + tig + 4];
                a[mt][3] = As[(r0 + 8) * 36 + kk + tig + 4];
            }
#pragma unroll
            for (int nt = 0; nt < 8; nt++) {
                int c0 = wn + nt * 8 + g;
                b[nt][0] = Bs[(kk + tig) * 136 + c0];
                b[nt][1] = Bs[(kk + tig + 4) * 136 + c0];
            }
#pragma unroll
            for (int mt = 0; mt < 2; mt++)
#pragma unroll
                for (int nt = 0; nt < 8; nt++) {
                    asm volatile(
                        "mma.sync.aligned.m16n8k8.row.col.f32.tf32.tf32.f32 "
                        "{%0,%1,%2,%3}, {%4,%5,%6,%7}, {%8,%9}, {%0,%1,%2,%3};"
                        : "+f"(acc[mt][nt][0]), "+f"(acc[mt][nt][1]),
                          "+f"(acc[mt][nt][2]), "+f"(acc[mt][nt][3])
                        : "r"(a[mt][0]), "r"(a[mt][1]),
                          "r"(a[mt][2]), "r"(a[mt][3]),
                          "r"(b[nt][0]), "r"(b[nt][1]));
                }
        }
        __syncthreads();
    }

    if (asrc == nullptr) {
#pragma unroll
        for (int mt = 0; mt < 2; mt++) {
            int row = bm + wm + mt * 16 + g;
#pragma unroll
            for (int nt = 0; nt < 8; nt++) {
                int col = wn + nt * 8 + 2 * tig;
                float bx = bias ? bias[col] : 0.f;
                float by = bias ? bias[col + 1] : 0.f;
                if (row < N_NODES)
                    *(float2*)(Cp + (size_t)row * D + col) =
                        make_float2(acc[mt][nt][0] + bx, acc[mt][nt][1] + by);
                if (row + 8 < N_NODES)
                    *(float2*)(Cp + (size_t)(row + 8) * D + col) =
                        make_float2(acc[mt][nt][2] + bx, acc[mt][nt][3] + by);
            }
        }
    } else {
        const int head_base = (wn == 0) ? 0 : 2;
#pragma unroll
        for (int mt = 0; mt < 2; mt++) {
#pragma unroll
            for (int rh = 0; rh < 2; rh++) {
                int row = bm + wm + mt * 16 + rh * 8 + g;
                float ps0 = 0.f, ps1 = 0.f, pd0 = 0.f, pd1 = 0.f;
#pragma unroll
                for (int nt = 0; nt < 8; nt++) {
                    int col = wn + nt * 8 + 2 * tig;
                    int c = (nt & 3) * 8 + 2 * tig;
                    int hl = nt >> 2;
                    float v0 = acc[mt][nt][rh * 2 + 0];
                    float v1 = acc[mt][nt][rh * 2 + 1];
                    float s0 = __ldg(asrc + (head_base + hl) * 32 + c);
                    float s1 = __ldg(asrc + (head_base + hl) * 32 + c + 1);
                    float d0 = __ldg(adst + (head_base + hl) * 32 + c);
                    float d1 = __ldg(adst + (head_base + hl) * 32 + c + 1);
                    if (hl == 0) { ps0 += v0 * s0 + v1 * s1; pd0 += v0 * d0 + v1 * d1; }
                    else         { ps1 += v0 * s0 + v1 * s1; pd1 += v0 * d0 + v1 * d1; }
                    if (row < N_NODES)
                        *(__half2*)(g_xph + (size_t)row * D + col) =
                            __floats2half2_rn(v0, v1);
                }
#pragma unroll
                for (int off = 1; off < 4; off <<= 1) {
                    ps0 += __shfl_xor_sync(0xffffffffu, ps0, off);
                    ps1 += __shfl_xor_sync(0xffffffffu, ps1, off);
                    pd0 += __shfl_xor_sync(0xffffffffu, pd0, off);
                    pd1 += __shfl_xor_sync(0xffffffffu, pd1, off);
                }
                if (tig == 0 && row < N_NODES) {
                    g_als[row * 4 + head_base]     = ps0;
                    g_als[row * 4 + head_base + 1] = ps1;
                    g_ald[row * 4 + head_base]     = pd0;
                    g_ald[row * 4 + head_base + 1] = pd1;
                }
            }
        }
    }
}

// ---------------- softmax-aggregate: one warp per destination node ----------------
// Edge indices preloaded coalesced (32/warp-load), broadcast via shfl;
// inner loop unrolled 2x with independent loads for MLP depth.
__global__ void k_agg(int in_sel, float* out_ext, int out_sel,
                      const float* __restrict__ bias, int relu_res) {
    int n = (blockIdx.x * blockDim.x + threadIdx.x) >> 5;
    if (n >= N_NODES) return;
    int lane = threadIdx.x & 31;
    const float* xin = (in_sel == 0) ? g_h : g_h2;
    float* outp = out_ext ? out_ext : (out_sel == 0 ? g_h : g_h2);
    int beg = g_rowptr[n], end = g_rowptr[n + 1];
    int hh = lane >> 3;
    float ad = g_ald[n * 4 + hh];

    float4 acc = make_float4(0.f, 0.f, 0.f, 0.f);
    float ssum = 0.f;

    for (int base = beg; base < end; base += 32) {
        int cnt = end - base;
        if (cnt > 32) cnt = 32;
        int sidx = g_col[base + (lane < cnt ? lane : cnt - 1)];  // coalesced
        int e = 0;
        for (; e + 2 <= cnt; e += 2) {
            int s0 = __shfl_sync(0xffffffffu, sidx, e);
            int s1 = __shfl_sync(0xffffffffu, sidx, e + 1);
            float a0 = __ldg(&g_als[(size_t)s0 * 4 + hh]);
            float a1 = __ldg(&g_als[(size_t)s1 * 4 + hh]);
            uint2 u0 = *(const uint2*)(g_xph + (size_t)s0 * D + lane * 4);
            uint2 u1 = *(const uint2*)(g_xph + (size_t)s1 * D + lane * 4);
            float e0 = a0 + ad; e0 = e0 > 0.f ? e0 : 0.2f * e0;
            float e1 = a1 + ad; e1 = e1 > 0.f ? e1 : 0.2f * e1;
            float p0 = __expf(e0);
            float p1 = __expf(e1);
            ssum += p0; ssum += p1;
            float2 f00 = __half22float2(*(__half2*)&u0.x);
            float2 f01 = __half22float2(*(__half2*)&u0.y);
            float2 f10 = __half22float2(*(__half2*)&u1.x);
            float2 f11 = __half22float2(*(__half2*)&u1.y);
            acc.x += p0 * f00.x; acc.y += p0 * f00.y;
            acc.z += p0 * f01.x; acc.w += p0 * f01.y;
            acc.x += p1 * f10.x; acc.y += p1 * f10.y;
            acc.z += p1 * f11.x; acc.w += p1 * f11.y;
        }
        if (e < cnt) {
            int s0 = __shfl_sync(0xffffffffu, sidx, e);
            float a0 = __ldg(&g_als[(size_t)s0 * 4 + hh]);
            uint2 u0 = *(const uint2*)(g_xph + (size_t)s0 * D + lane * 4);
            float e0 = a0 + ad; e0 = e0 > 0.f ? e0 : 0.2f * e0;
            float p0 = __expf(e0);
            ssum += p0;
            float2 f00 = __half22float2(*(__half2*)&u0.x);
            float2 f01 = __half22float2(*(__half2*)&u0.y);
            acc.x += p0 * f00.x; acc.y += p0 * f00.y;
            acc.z += p0 * f01.x; acc.w += p0 * f01.y;
        }
    }

    float inv = 1.f / ssum;
    float4 bv = *(const float4*)(bias + lane * 4);
    float4 o;
    o.x = acc.x * inv + bv.x;
    o.y = acc.y * inv + bv.y;
    o.z = acc.z * inv + bv.z;
    o.w = acc.w * inv + bv.w;
    if (relu_res) {
        float4 r = *(const float4*)(xin + (size_t)n * D + lane * 4);
        o.x = fmaxf(o.x + r.x, 0.f);
        o.y = fmaxf(o.y + r.y, 0.f);
        o.z = fmaxf(o.z + r.z, 0.f);
        o.w = fmaxf(o.w + r.w, 0.f);
    }
    *(float4*)(outp + (size_t)n * D + lane * 4) = o;
}

// ---------------- launch ----------------
extern "C" void kernel_launch(void* const* d_in, const int* in_sizes, int n_in,
                              void* d_out, int out_size) {
    const float* x   = (const float*)d_in[0];
    const int*   ei  = (const int*)  d_in[1];
    const float* w0  = (const float*)d_in[2];
    const float* b0  = (const float*)d_in[3];
    const float* w1  = (const float*)d_in[4];
    const float* as1 = (const float*)d_in[5];
    const float* ad1 = (const float*)d_in[6];
    const float* b1  = (const float*)d_in[7];
    const float* w2  = (const float*)d_in[8];
    const float* as2 = (const float*)d_in[9];
    const float* ad2 = (const float*)d_in[10];
    const float* b2  = (const float*)d_in[11];
    const float* w3  = (const float*)d_in[12];
    const float* as3 = (const float*)d_in[13];
    const float* ad3 = (const float*)d_in[14];
    const float* b3  = (const float*)d_in[15];
    float* out = (float*)d_out;

    int ggrid = (N_NODES + 127) / 128;      // 391 blocks
    int wgrid = (N_NODES * 32) / 256;       // 6250 blocks, 1 warp per node

    // CSR (4 launches; g_deg self-cleans inside k_scan1)
    k_count<<<(N_EDGES + 255) / 256, 256>>>(ei);          // 0
    k_scan1<<<NB, 1024>>>();                              // 1
    k_scan3<<<(N_NODES + 255) / 256, 256>>>();            // 2
    k_scatter<<<(N_NODES + N_EDGES + 255) / 256, 256>>>(ei); // 3

    // h0 = x @ w0 + b0  -> g_h
    k_gemm_tc<<<ggrid, 256>>>(x, 0, w0, b0, 0, nullptr, nullptr);     // 4

    // layer 1: in g_h -> out g_h2
    k_gemm_tc<<<ggrid, 256>>>(nullptr, 0, w1, nullptr, 2, as1, ad1);  // 5 (profiled)
    k_agg<<<wgrid, 256>>>(0, nullptr, 1, b1, 1);                      // 6

    // layer 2: in g_h2 -> out g_h
    k_gemm_tc<<<ggrid, 256>>>(nullptr, 1, w2, nullptr, 2, as2, ad2);  // 7
    k_agg<<<wgrid, 256>>>(1, nullptr, 0, b2, 1);                      // 8

    // layer 3: in g_h -> d_out
    k_gemm_tc<<<ggrid, 256>>>(nullptr, 0, w3, nullptr, 2, as3, ad3);  // 9
    k_agg<<<wgrid, 256>>>(0, out, 0, b3, 0);                          // 10
}

// round 5
// speedup vs baseline: 1.1712x; 1.1712x over previous
#include <cuda_runtime.h>
#include <cuda_fp16.h>
#include <cstdint>

#define N_NODES 50000
#define N_EDGES 800000
#define E_TOT   (N_EDGES + N_NODES)
#define D 128
#define H 4
#define NB ((N_NODES + 1023) / 1024)   // 49 scan blocks

// ---------------- scratch (static device globals; no allocs) ----------------
__device__ __align__(16) float  g_h  [N_NODES * D];
__device__ __align__(16) float  g_h2 [N_NODES * D];
__device__ __align__(16) __half g_xph[N_NODES * D];   // fp16 message mirror
__device__ __align__(16) float  g_als[N_NODES * H];
__device__ __align__(16) float  g_ald[N_NODES * H];
__device__ int g_deg[N_NODES];        // zero-initialized; re-zeroed by k_scan1
__device__ int g_rowptr[N_NODES + 1];
__device__ int g_wp[N_NODES];
__device__ int g_col[E_TOT];
__device__ int g_bsum[64];

// ---------------- CSR build (4 kernels) ----------------
__global__ void k_count(const int* __restrict__ ei) {
    int i = blockIdx.x * blockDim.x + threadIdx.x;
    if (i < N_EDGES) atomicAdd(&g_deg[ei[N_EDGES + i]], 1);
}

// block-wise exclusive scan of (deg+1); also consumes & re-zeroes deg.
__global__ void k_scan1() {
    __shared__ int sm[1024];
    int i = blockIdx.x * 1024 + threadIdx.x;
    int v = 0;
    if (i < N_NODES) {
        v = g_deg[i] + 1;          // +1 = self loop
        g_deg[i] = 0;              // clean state for next replay
    }
    sm[threadIdx.x] = v;
    __syncthreads();
    for (int off = 1; off < 1024; off <<= 1) {
        int t = (threadIdx.x >= off) ? sm[threadIdx.x - off] : 0;
        __syncthreads();
        sm[threadIdx.x] += t;
        __syncthreads();
    }
    if (i < N_NODES) g_rowptr[i] = sm[threadIdx.x] - v;   // exclusive in-block
    if (threadIdx.x == 1023) g_bsum[blockIdx.x] = sm[1023];
}

// apply block offsets; each block redundantly scans the 49 block sums.
__global__ void k_scan3() {
    __shared__ int sb[64];
    __shared__ int sb_ex[64];
    int t = threadIdx.x;
    if (t < 64) sb[t] = (t < NB) ? g_bsum[t] : 0;
    __syncthreads();
    for (int off = 1; off < 64; off <<= 1) {
        int x = (t < 64 && t >= off) ? sb[t - off] : 0;
        __syncthreads();
        if (t < 64) sb[t] += x;
        __syncthreads();
    }
    if (t < 64) sb_ex[t] = (t == 0) ? 0 : sb[t - 1];
    __syncthreads();
    int i = blockIdx.x * blockDim.x + t;
    if (i < N_NODES) {
        int r = g_rowptr[i] + sb_ex[i >> 10];
        g_rowptr[i] = r;
        g_wp[i] = r;
    }
    if (i == 0) g_rowptr[N_NODES] = E_TOT;
}

__global__ void k_scatter(const int* __restrict__ ei) {
    int i = blockIdx.x * blockDim.x + threadIdx.x;
    if (i < N_NODES) {
        int p = atomicAdd(&g_wp[i], 1);
        g_col[p] = i;                          // self loop
    } else if (i < N_NODES + N_EDGES) {
        int j = i - N_NODES;
        int s = ei[j], d = ei[N_EDGES + j];
        int p = atomicAdd(&g_wp[d], 1);
        g_col[p] = s;
    }
}

// ---------------- tf32 tensor-core GEMM ----------------
// C[N,128] = A[N,128] @ W[128,128], BM=128 BN=128 BK=32, 256 thr.
// asrc==null: fp32 (+bias) epilogue. asrc!=null: fp16 mirror + fused logits.
__device__ __forceinline__ uint32_t f2tf32(float f) {
    uint32_t r;
    asm("cvt.rna.tf32.f32 %0, %1;" : "=r"(r) : "f"(f));
    return r;
}

__global__ void __launch_bounds__(256) k_gemm_tc(
        const float* Aext, int asel,
        const float* __restrict__ W,
        const float* __restrict__ bias,
        int csel,
        const float* __restrict__ asrc,
        const float* __restrict__ adst) {
    __shared__ uint32_t As[128 * 36];   // [m][k], stride 36
    __shared__ uint32_t Bs[32 * 136];   // [k][n], stride 136

    const float* A = Aext ? Aext : (asel == 0 ? g_h : g_h2);
    float* Cp = (csel == 0 ? g_h : g_h2);

    const int bm = blockIdx.x * 128;
    const int tid = threadIdx.x;
    const int wid = tid >> 5, lane = tid & 31;
    const int g = lane >> 2, tig = lane & 3;
    const int wm = (wid & 3) * 32;
    const int wn = (wid >> 2) * 64;

    float acc[2][8][4];
#pragma unroll
    for (int mt = 0; mt < 2; mt++)
#pragma unroll
        for (int nt = 0; nt < 8; nt++)
#pragma unroll
            for (int q = 0; q < 4; q++) acc[mt][nt][q] = 0.f;

    for (int k0 = 0; k0 < 128; k0 += 32) {
#pragma unroll
        for (int it = 0; it < 4; it++) {
            int idx = tid + 256 * it;
            int row = idx >> 3, c4 = (idx & 7) << 2;
            float4 v = make_float4(0.f, 0.f, 0.f, 0.f);
            if (bm + row < N_NODES)
                v = *(const float4*)(A + (size_t)(bm + row) * D + k0 + c4);
            uint32_t* p = &As[row * 36 + c4];
            p[0] = f2tf32(v.x); p[1] = f2tf32(v.y);
            p[2] = f2tf32(v.z); p[3] = f2tf32(v.w);
        }
#pragma unroll
        for (int it = 0; it < 4; it++) {
            int idx = tid + 256 * it;
            int row = idx >> 5, c4 = (idx & 31) << 2;
            float4 v = *(const float4*)(W + (size_t)(k0 + row) * D + c4);
            uint32_t* p = &Bs[row * 136 + c4];
            p[0] = f2tf32(v.x); p[1] = f2tf32(v.y);
            p[2] = f2tf32(v.z); p[3] = f2tf32(v.w);
        }
        __syncthreads();

#pragma unroll
        for (int kk = 0; kk < 32; kk += 8) {
            uint32_t a[2][4], b[8][2];
#pragma unroll
            for (int mt = 0; mt < 2; mt++) {
                int r0 = wm + mt * 16 + g;
                a[mt][0] = As[r0 * 36 + kk + tig];
                a[mt][1] = As[(r0 + 8) * 36 + kk + tig];
                a[mt][2] = As[r0 * 36 + kk + tig + 4];
                a[mt][3] = As[(r0 + 8) * 36 + kk + tig + 4];
            }
#pragma unroll
            for (int nt = 0; nt < 8; nt++) {
                int c0 = wn + nt * 8 + g;
                b[nt][0] = Bs[(kk + tig) * 136 + c0];
                b[nt][1] = Bs[(kk + tig + 4) * 136 + c0];
            }
#pragma unroll
            for (int mt = 0; mt < 2; mt++)
#pragma unroll
                for (int nt = 0; nt < 8; nt++) {
                    asm volatile(
                        "mma.sync.aligned.m16n8k8.row.col.f32.tf32.tf32.f32 "
                        "{%0,%1,%2,%3}, {%4,%5,%6,%7}, {%8,%9}, {%0,%1,%2,%3};"
                        : "+f"(acc[mt][nt][0]), "+f"(acc[mt][nt][1]),
                          "+f"(acc[mt][nt][2]), "+f"(acc[mt][nt][3])
                        : "r"(a[mt][0]), "r"(a[mt][1]),
                          "r"(a[mt][2]), "r"(a[mt][3]),
                          "r"(b[nt][0]), "r"(b[nt][1]));
                }
        }
        __syncthreads();
    }

    if (asrc == nullptr) {
#pragma unroll
        for (int mt = 0; mt < 2; mt++) {
            int row = bm + wm + mt * 16 + g;
#pragma unroll
            for (int nt = 0; nt < 8; nt++) {
                int col = wn + nt * 8 + 2 * tig;
                float bx = bias ? bias[col] : 0.f;
                float by = bias ? bias[col + 1] : 0.f;
                if (row < N_NODES)
                    *(float2*)(Cp + (size_t)row * D + col) =
                        make_float2(acc[mt][nt][0] + bx, acc[mt][nt][1] + by);
                if (row + 8 < N_NODES)
                    *(float2*)(Cp + (size_t)(row + 8) * D + col) =
                        make_float2(acc[mt][nt][2] + bx, acc[mt][nt][3] + by);
            }
        }
    } else {
        const int head_base = (wn == 0) ? 0 : 2;
#pragma unroll
        for (int mt = 0; mt < 2; mt++) {
#pragma unroll
            for (int rh = 0; rh < 2; rh++) {
                int row = bm + wm + mt * 16 + rh * 8 + g;
                float ps0 = 0.f, ps1 = 0.f, pd0 = 0.f, pd1 = 0.f;
#pragma unroll
                for (int nt = 0; nt < 8; nt++) {
                    int col = wn + nt * 8 + 2 * tig;
                    int c = (nt & 3) * 8 + 2 * tig;
                    int hl = nt >> 2;
                    float v0 = acc[mt][nt][rh * 2 + 0];
                    float v1 = acc[mt][nt][rh * 2 + 1];
                    float s0 = __ldg(asrc + (head_base + hl) * 32 + c);
                    float s1 = __ldg(asrc + (head_base + hl) * 32 + c + 1);
                    float d0 = __ldg(adst + (head_base + hl) * 32 + c);
                    float d1 = __ldg(adst + (head_base + hl) * 32 + c + 1);
                    if (hl == 0) { ps0 += v0 * s0 + v1 * s1; pd0 += v0 * d0 + v1 * d1; }
                    else         { ps1 += v0 * s0 + v1 * s1; pd1 += v0 * d0 + v1 * d1; }
                    if (row < N_NODES)
                        *(__half2*)(g_xph + (size_t)row * D + col) =
                            __floats2half2_rn(v0, v1);
                }
#pragma unroll
                for (int off = 1; off < 4; off <<= 1) {
                    ps0 += __shfl_xor_sync(0xffffffffu, ps0, off);
                    ps1 += __shfl_xor_sync(0xffffffffu, ps1, off);
                    pd0 += __shfl_xor_sync(0xffffffffu, pd0, off);
                    pd1 += __shfl_xor_sync(0xffffffffu, pd1, off);
                }
                if (tig == 0 && row < N_NODES) {
                    g_als[row * 4 + head_base]     = ps0;
                    g_als[row * 4 + head_base + 1] = ps1;
                    g_ald[row * 4 + head_base]     = pd0;
                    g_ald[row * 4 + head_base + 1] = pd1;
                }
            }
        }
    }
}

// ---------------- softmax-aggregate: one warp per destination node ----------------
// Direct broadcast loads of g_col (L1-hit, pipelined — NO shfl in dependency
// chain), 2-edge unroll so both edges' als+xph loads are in flight together.
__global__ void k_agg(int in_sel, float* out_ext, int out_sel,
                      const float* __restrict__ bias, int relu_res) {
    int n = (blockIdx.x * blockDim.x + threadIdx.x) >> 5;
    if (n >= N_NODES) return;
    int lane = threadIdx.x & 31;
    const float* xin = (in_sel == 0) ? g_h : g_h2;
    float* outp = out_ext ? out_ext : (out_sel == 0 ? g_h : g_h2);
    int beg = g_rowptr[n], end = g_rowptr[n + 1];
    int hh = lane >> 3;
    float ad = g_ald[n * 4 + hh];

    float4 acc = make_float4(0.f, 0.f, 0.f, 0.f);
    float ssum = 0.f;

    int j = beg;
    for (; j + 2 <= end; j += 2) {
        int s0 = __ldg(&g_col[j]);        // broadcast, independent
        int s1 = __ldg(&g_col[j + 1]);    // broadcast, independent
        float a0 = __ldg(&g_als[(size_t)s0 * 4 + hh]);
        float a1 = __ldg(&g_als[(size_t)s1 * 4 + hh]);
        uint2 u0 = *(const uint2*)(g_xph + (size_t)s0 * D + lane * 4);
        uint2 u1 = *(const uint2*)(g_xph + (size_t)s1 * D + lane * 4);
        float e0 = a0 + ad; e0 = e0 > 0.f ? e0 : 0.2f * e0;
        float e1 = a1 + ad; e1 = e1 > 0.f ? e1 : 0.2f * e1;
        float p0 = __expf(e0);
        float p1 = __expf(e1);
        ssum += p0; ssum += p1;
        float2 f00 = __half22float2(*(__half2*)&u0.x);
        float2 f01 = __half22float2(*(__half2*)&u0.y);
        float2 f10 = __half22float2(*(__half2*)&u1.x);
        float2 f11 = __half22float2(*(__half2*)&u1.y);
        acc.x += p0 * f00.x; acc.y += p0 * f00.y;
        acc.z += p0 * f01.x; acc.w += p0 * f01.y;
        acc.x += p1 * f10.x; acc.y += p1 * f10.y;
        acc.z += p1 * f11.x; acc.w += p1 * f11.y;
    }
    if (j < end) {
        int s0 = __ldg(&g_col[j]);
        float a0 = __ldg(&g_als[(size_t)s0 * 4 + hh]);
        uint2 u0 = *(const uint2*)(g_xph + (size_t)s0 * D + lane * 4);
        float e0 = a0 + ad; e0 = e0 > 0.f ? e0 : 0.2f * e0;
        float p0 = __expf(e0);
        ssum += p0;
        float2 f00 = __half22float2(*(__half2*)&u0.x);
        float2 f01 = __half22float2(*(__half2*)&u0.y);
        acc.x += p0 * f00.x; acc.y += p0 * f00.y;
        acc.z += p0 * f01.x; acc.w += p0 * f01.y;
    }

    float inv = 1.f / ssum;
    float4 bv = *(const float4*)(bias + lane * 4);
    float4 o;
    o.x = acc.x * inv + bv.x;
    o.y = acc.y * inv + bv.y;
    o.z = acc.z * inv + bv.z;
    o.w = acc.w * inv + bv.w;
    if (relu_res) {
        float4 r = *(const float4*)(xin + (size_t)n * D + lane * 4);
        o.x = fmaxf(o.x + r.x, 0.f);
        o.y = fmaxf(o.y + r.y, 0.f);
        o.z = fmaxf(o.z + r.z, 0.f);
        o.w = fmaxf(o.w + r.w, 0.f);
    }
    *(float4*)(outp + (size_t)n * D + lane * 4) = o;
}

// ---------------- launch ----------------
extern "C" void kernel_launch(void* const* d_in, const int* in_sizes, int n_in,
                              void* d_out, int out_size) {
    const float* x   = (const float*)d_in[0];
    const int*   ei  = (const int*)  d_in[1];
    const float* w0  = (const float*)d_in[2];
    const float* b0  = (const float*)d_in[3];
    const float* w1  = (const float*)d_in[4];
    const float* as1 = (const float*)d_in[5];
    const float* ad1 = (const float*)d_in[6];
    const float* b1  = (const float*)d_in[7];
    const float* w2  = (const float*)d_in[8];
    const float* as2 = (const float*)d_in[9];
    const float* ad2 = (const float*)d_in[10];
    const float* b2  = (const float*)d_in[11];
    const float* w3  = (const float*)d_in[12];
    const float* as3 = (const float*)d_in[13];
    const float* ad3 = (const float*)d_in[14];
    const float* b3  = (const float*)d_in[15];
    float* out = (float*)d_out;

    int ggrid = (N_NODES + 127) / 128;      // 391 blocks
    int wgrid = (N_NODES * 32) / 256;       // 6250 blocks, 1 warp per node

    // CSR (4 launches; g_deg self-cleans inside k_scan1)
    k_count<<<(N_EDGES + 255) / 256, 256>>>(ei);             // 0
    k_scan1<<<NB, 1024>>>();                                 // 1
    k_scan3<<<(N_NODES + 255) / 256, 256>>>();               // 2
    k_scatter<<<(N_NODES + N_EDGES + 255) / 256, 256>>>(ei); // 3

    // h0 = x @ w0 + b0  -> g_h
    k_gemm_tc<<<ggrid, 256>>>(x, 0, w0, b0, 0, nullptr, nullptr);     // 4

    // layer 1: in g_h -> out g_h2
    k_gemm_tc<<<ggrid, 256>>>(nullptr, 0, w1, nullptr, 2, as1, ad1);  // 5
    k_agg<<<wgrid, 256>>>(0, nullptr, 1, b1, 1);                      // 6

    // layer 2: in g_h2 -> out g_h
    k_gemm_tc<<<ggrid, 256>>>(nullptr, 1, w2, nullptr, 2, as2, ad2);  // 7
    k_agg<<<wgrid, 256>>>(1, nullptr, 0, b2, 1);                      // 8

    // layer 3: in g_h -> d_out
    k_gemm_tc<<<ggrid, 256>>>(nullptr, 0, w3, nullptr, 2, as3, ad3);  // 9
    k_agg<<<wgrid, 256>>>(0, out, 0, b3, 0);                          // 10
}

// round 6
// speedup vs baseline: 1.2505x; 1.0676x over previous
#include <cuda_runtime.h>
#include <cuda_fp16.h>
#include <cstdint>

#define N_NODES 50000
#define N_EDGES 800000
#define E_TOT   (N_EDGES + N_NODES)
#define D 128
#define H 4
#define NB ((N_NODES + 1023) / 1024)       // 49 scan blocks (1024 nodes each)
#define GGRID ((N_NODES + 127) / 128)      // 391 gemm blocks
#define CNT_BLK ((N_EDGES + 255) / 256)    // 3125 count blocks

// ---------------- scratch (static device globals; no allocs) ----------------
__device__ __align__(16) float  g_h  [N_NODES * D];
__device__ __align__(16) float  g_h2 [N_NODES * D];
__device__ __align__(16) __half g_xph[N_NODES * D];   // fp16 message mirror
__device__ __align__(16) float  g_als[N_NODES * H];
__device__ __align__(16) float  g_ald[N_NODES * H];
__device__ int g_deg[N_NODES];        // zero-initialized; re-zeroed by scan1
__device__ int g_rowptr[N_NODES + 1];
__device__ int g_wp[N_NODES];
__device__ int g_col[E_TOT];
__device__ int g_bsum[64];

// ---------------- tf32 GEMM body (device fn; fat-kernel friendly) ----------------
__device__ __forceinline__ uint32_t f2tf32(float f) {
    uint32_t r;
    asm("cvt.rna.tf32.f32 %0, %1;" : "=r"(r) : "f"(f));
    return r;
}

__device__ void gemm_body(
        const float* Aext, int asel,
        const float* __restrict__ W,
        const float* __restrict__ bias,
        int csel,
        const float* __restrict__ asrc,
        const float* __restrict__ adst,
        int bidx) {
    __shared__ uint32_t As[128 * 36];   // [m][k], stride 36
    __shared__ uint32_t Bs[32 * 136];   // [k][n], stride 136

    const float* A = Aext ? Aext : (asel == 0 ? g_h : g_h2);
    float* Cp = (csel == 0 ? g_h : g_h2);

    const int bm = bidx * 128;
    const int tid = threadIdx.x;
    const int wid = tid >> 5, lane = tid & 31;
    const int g = lane >> 2, tig = lane & 3;
    const int wm = (wid & 3) * 32;
    const int wn = (wid >> 2) * 64;

    float acc[2][8][4];
#pragma unroll
    for (int mt = 0; mt < 2; mt++)
#pragma unroll
        for (int nt = 0; nt < 8; nt++)
#pragma unroll
            for (int q = 0; q < 4; q++) acc[mt][nt][q] = 0.f;

    for (int k0 = 0; k0 < 128; k0 += 32) {
#pragma unroll
        for (int it = 0; it < 4; it++) {
            int idx = tid + 256 * it;
            int row = idx >> 3, c4 = (idx & 7) << 2;
            float4 v = make_float4(0.f, 0.f, 0.f, 0.f);
            if (bm + row < N_NODES)
                v = *(const float4*)(A + (size_t)(bm + row) * D + k0 + c4);
            uint32_t* p = &As[row * 36 + c4];
            p[0] = f2tf32(v.x); p[1] = f2tf32(v.y);
            p[2] = f2tf32(v.z); p[3] = f2tf32(v.w);
        }
#pragma unroll
        for (int it = 0; it < 4; it++) {
            int idx = tid + 256 * it;
            int row = idx >> 5, c4 = (idx & 31) << 2;
            float4 v = *(const float4*)(W + (size_t)(k0 + row) * D + c4);
            uint32_t* p = &Bs[row * 136 + c4];
            p[0] = f2tf32(v.x); p[1] = f2tf32(v.y);
            p[2] = f2tf32(v.z); p[3] = f2tf32(v.w);
        }
        __syncthreads();

#pragma unroll
        for (int kk = 0; kk < 32; kk += 8) {
            uint32_t a[2][4], b[8][2];
#pragma unroll
            for (int mt = 0; mt < 2; mt++) {
                int r0 = wm + mt * 16 + g;
                a[mt][0] = As[r0 * 36 + kk + tig];
                a[mt][1] = As[(r0 + 8) * 36 + kk + tig];
                a[mt][2] = As[r0 * 36 + kk + tig + 4];
                a[mt][3] = As[(r0 + 8) * 36 + kk + tig + 4];
            }
#pragma unroll
            for (int nt = 0; nt < 8; nt++) {
                int c0 = wn + nt * 8 + g;
                b[nt][0] = Bs[(kk + tig) * 136 + c0];
                b[nt][1] = Bs[(kk + tig + 4) * 136 + c0];
            }
#pragma unroll
            for (int mt = 0; mt < 2; mt++)
#pragma unroll
                for (int nt = 0; nt < 8; nt++) {
                    asm volatile(
                        "mma.sync.aligned.m16n8k8.row.col.f32.tf32.tf32.f32 "
                        "{%0,%1,%2,%3}, {%4,%5,%6,%7}, {%8,%9}, {%0,%1,%2,%3};"
                        : "+f"(acc[mt][nt][0]), "+f"(acc[mt][nt][1]),
                          "+f"(acc[mt][nt][2]), "+f"(acc[mt][nt][3])
                        : "r"(a[mt][0]), "r"(a[mt][1]),
                          "r"(a[mt][2]), "r"(a[mt][3]),
                          "r"(b[nt][0]), "r"(b[nt][1]));
                }
        }
        __syncthreads();
    }

    if (asrc == nullptr) {
#pragma unroll
        for (int mt = 0; mt < 2; mt++) {
            int row = bm + wm + mt * 16 + g;
#pragma unroll
            for (int nt = 0; nt < 8; nt++) {
                int col = wn + nt * 8 + 2 * tig;
                float bx = bias ? bias[col] : 0.f;
                float by = bias ? bias[col + 1] : 0.f;
                if (row < N_NODES)
                    *(float2*)(Cp + (size_t)row * D + col) =
                        make_float2(acc[mt][nt][0] + bx, acc[mt][nt][1] + by);
                if (row + 8 < N_NODES)
                    *(float2*)(Cp + (size_t)(row + 8) * D + col) =
                        make_float2(acc[mt][nt][2] + bx, acc[mt][nt][3] + by);
            }
        }
    } else {
        const int head_base = (wn == 0) ? 0 : 2;
#pragma unroll
        for (int mt = 0; mt < 2; mt++) {
#pragma unroll
            for (int rh = 0; rh < 2; rh++) {
                int row = bm + wm + mt * 16 + rh * 8 + g;
                float ps0 = 0.f, ps1 = 0.f, pd0 = 0.f, pd1 = 0.f;
#pragma unroll
                for (int nt = 0; nt < 8; nt++) {
                    int col = wn + nt * 8 + 2 * tig;
                    int c = (nt & 3) * 8 + 2 * tig;
                    int hl = nt >> 2;
                    float v0 = acc[mt][nt][rh * 2 + 0];
                    float v1 = acc[mt][nt][rh * 2 + 1];
                    float s0 = __ldg(asrc + (head_base + hl) * 32 + c);
                    float s1 = __ldg(asrc + (head_base + hl) * 32 + c + 1);
                    float d0 = __ldg(adst + (head_base + hl) * 32 + c);
                    float d1 = __ldg(adst + (head_base + hl) * 32 + c + 1);
                    if (hl == 0) { ps0 += v0 * s0 + v1 * s1; pd0 += v0 * d0 + v1 * d1; }
                    else         { ps1 += v0 * s0 + v1 * s1; pd1 += v0 * d0 + v1 * d1; }
                    if (row < N_NODES)
                        *(__half2*)(g_xph + (size_t)row * D + col) =
                            __floats2half2_rn(v0, v1);
                }
#pragma unroll
                for (int off = 1; off < 4; off <<= 1) {
                    ps0 += __shfl_xor_sync(0xffffffffu, ps0, off);
                    ps1 += __shfl_xor_sync(0xffffffffu, ps1, off);
                    pd0 += __shfl_xor_sync(0xffffffffu, pd0, off);
                    pd1 += __shfl_xor_sync(0xffffffffu, pd1, off);
                }
                if (tig == 0 && row < N_NODES) {
                    g_als[row * 4 + head_base]     = ps0;
                    g_als[row * 4 + head_base + 1] = ps1;
                    g_ald[row * 4 + head_base]     = pd0;
                    g_ald[row * 4 + head_base + 1] = pd1;
                }
            }
        }
    }
}

// ---------------- scan1 body: 256-thr block scans 1024 nodes ----------------
// exclusive scan of (deg+1); consumes & re-zeroes deg; bsum[b] = block total.
__device__ void scan1_body(int b) {
    __shared__ int sm[256];
    int t = threadIdx.x;
    int base = b * 1024 + t * 4;
    int v0 = 0, v1 = 0, v2 = 0, v3 = 0;
    if (base + 3 < N_NODES) {
        int4 d = *(int4*)&g_deg[base];
        v0 = d.x + 1; v1 = d.y + 1; v2 = d.z + 1; v3 = d.w + 1;
        *(int4*)&g_deg[base] = make_int4(0, 0, 0, 0);
    } else {
        if (base + 0 < N_NODES) { v0 = g_deg[base + 0] + 1; g_deg[base + 0] = 0; }
        if (base + 1 < N_NODES) { v1 = g_deg[base + 1] + 1; g_deg[base + 1] = 0; }
        if (base + 2 < N_NODES) { v2 = g_deg[base + 2] + 1; g_deg[base + 2] = 0; }
        if (base + 3 < N_NODES) { v3 = g_deg[base + 3] + 1; g_deg[base + 3] = 0; }
    }
    int s = v0 + v1 + v2 + v3;
    sm[t] = s;
    __syncthreads();
#pragma unroll
    for (int off = 1; off < 256; off <<= 1) {
        int x = (t >= off) ? sm[t - off] : 0;
        __syncthreads();
        sm[t] += x;
        __syncthreads();
    }
    int run = sm[t] - s;                       // exclusive within block
    if (base + 0 < N_NODES) g_rowptr[base + 0] = run; run += v0;
    if (base + 1 < N_NODES) g_rowptr[base + 1] = run; run += v1;
    if (base + 2 < N_NODES) g_rowptr[base + 2] = run; run += v2;
    if (base + 3 < N_NODES) g_rowptr[base + 3] = run;
    if (t == 255) g_bsum[b] = sm[255];
}

// ---------------- fat kernels: GEMM ∥ CSR stage ----------------
__global__ void __launch_bounds__(256) k_fused0(
        const float* x, const float* __restrict__ w0,
        const float* __restrict__ b0, const int* __restrict__ ei) {
    if (blockIdx.x < GGRID) {
        gemm_body(x, 0, w0, b0, 0, nullptr, nullptr, blockIdx.x);
    } else {
        int i = (blockIdx.x - GGRID) * 256 + threadIdx.x;
        if (i < N_EDGES) atomicAdd(&g_deg[ei[N_EDGES + i]], 1);
    }
}

__global__ void __launch_bounds__(256) k_fused1(
        const float* __restrict__ W,
        const float* __restrict__ asrc, const float* __restrict__ adst) {
    if (blockIdx.x < GGRID) {
        gemm_body(nullptr, 0, W, nullptr, 0, asrc, adst, blockIdx.x);
    } else {
        scan1_body(blockIdx.x - GGRID);
    }
}

// plain GEMM launcher for layers 2/3
__global__ void __launch_bounds__(256) k_gemm_tc(
        const float* Aext, int asel,
        const float* __restrict__ W,
        const float* __restrict__ bias,
        int csel,
        const float* __restrict__ asrc,
        const float* __restrict__ adst) {
    gemm_body(Aext, asel, W, bias, csel, asrc, adst, blockIdx.x);
}

// ---------------- remaining CSR kernels ----------------
__global__ void k_scan3() {
    __shared__ int sb[64];
    __shared__ int sb_ex[64];
    int t = threadIdx.x;
    if (t < 64) sb[t] = (t < NB) ? g_bsum[t] : 0;
    __syncthreads();
    for (int off = 1; off < 64; off <<= 1) {
        int x = (t < 64 && t >= off) ? sb[t - off] : 0;
        __syncthreads();
        if (t < 64) sb[t] += x;
        __syncthreads();
    }
    if (t < 64) sb_ex[t] = (t == 0) ? 0 : sb[t - 1];
    __syncthreads();
    int i = blockIdx.x * blockDim.x + t;
    if (i < N_NODES) {
        int r = g_rowptr[i] + sb_ex[i >> 10];
        g_rowptr[i] = r;
        g_wp[i] = r;
    }
    if (i == 0) g_rowptr[N_NODES] = E_TOT;
}

__global__ void k_scatter(const int* __restrict__ ei) {
    int i = blockIdx.x * blockDim.x + threadIdx.x;
    if (i < N_NODES) {
        int p = atomicAdd(&g_wp[i], 1);
        g_col[p] = i;                          // self loop
    } else if (i < N_NODES + N_EDGES) {
        int j = i - N_NODES;
        int s = ei[j], d = ei[N_EDGES + j];
        int p = atomicAdd(&g_wp[d], 1);
        g_col[p] = s;
    }
}

// ---------------- softmax-aggregate: one warp per destination node ----------------
// Broadcast LDG of indices (no shfl in chain); 4-edge unroll for MLP depth.
__global__ void k_agg(int in_sel, float* out_ext, int out_sel,
                      const float* __restrict__ bias, int relu_res) {
    int n = (blockIdx.x * blockDim.x + threadIdx.x) >> 5;
    if (n >= N_NODES) return;
    int lane = threadIdx.x & 31;
    const float* xin = (in_sel == 0) ? g_h : g_h2;
    float* outp = out_ext ? out_ext : (out_sel == 0 ? g_h : g_h2);
    int beg = g_rowptr[n], end = g_rowptr[n + 1];
    int hh = lane >> 3;
    float ad = g_ald[n * 4 + hh];

    float4 acc = make_float4(0.f, 0.f, 0.f, 0.f);
    float ssum = 0.f;

    int j = beg;
    for (; j + 4 <= end; j += 4) {
        int s0 = __ldg(&g_col[j]);
        int s1 = __ldg(&g_col[j + 1]);
        int s2 = __ldg(&g_col[j + 2]);
        int s3 = __ldg(&g_col[j + 3]);
        float a0 = __ldg(&g_als[(size_t)s0 * 4 + hh]);
        float a1 = __ldg(&g_als[(size_t)s1 * 4 + hh]);
        float a2 = __ldg(&g_als[(size_t)s2 * 4 + hh]);
        float a3 = __ldg(&g_als[(size_t)s3 * 4 + hh]);
        uint2 u0 = *(const uint2*)(g_xph + (size_t)s0 * D + lane * 4);
        uint2 u1 = *(const uint2*)(g_xph + (size_t)s1 * D + lane * 4);
        uint2 u2 = *(const uint2*)(g_xph + (size_t)s2 * D + lane * 4);
        uint2 u3 = *(const uint2*)(g_xph + (size_t)s3 * D + lane * 4);
        float e0 = a0 + ad; e0 = e0 > 0.f ? e0 : 0.2f * e0;
        float e1 = a1 + ad; e1 = e1 > 0.f ? e1 : 0.2f * e1;
        float e2 = a2 + ad; e2 = e2 > 0.f ? e2 : 0.2f * e2;
        float e3 = a3 + ad; e3 = e3 > 0.f ? e3 : 0.2f * e3;
        float p0 = __expf(e0), p1 = __expf(e1);
        float p2 = __expf(e2), p3 = __expf(e3);
        ssum += p0 + p1 + p2 + p3;
        float2 f00 = __half22float2(*(__half2*)&u0.x);
        float2 f01 = __half22float2(*(__half2*)&u0.y);
        float2 f10 = __half22float2(*(__half2*)&u1.x);
        float2 f11 = __half22float2(*(__half2*)&u1.y);
        float2 f20 = __half22float2(*(__half2*)&u2.x);
        float2 f21 = __half22float2(*(__half2*)&u2.y);
        float2 f30 = __half22float2(*(__half2*)&u3.x);
        float2 f31 = __half22float2(*(__half2*)&u3.y);
        acc.x += p0 * f00.x; acc.y += p0 * f00.y;
        acc.z += p0 * f01.x; acc.w += p0 * f01.y;
        acc.x += p1 * f10.x; acc.y += p1 * f10.y;
        acc.z += p1 * f11.x; acc.w += p1 * f11.y;
        acc.x += p2 * f20.x; acc.y += p2 * f20.y;
        acc.z += p2 * f21.x; acc.w += p2 * f21.y;
        acc.x += p3 * f30.x; acc.y += p3 * f30.y;
        acc.z += p3 * f31.x; acc.w += p3 * f31.y;
    }
    for (; j < end; j++) {
        int s0 = __ldg(&g_col[j]);
        float a0 = __ldg(&g_als[(size_t)s0 * 4 + hh]);
        uint2 u0 = *(const uint2*)(g_xph + (size_t)s0 * D + lane * 4);
        float e0 = a0 + ad; e0 = e0 > 0.f ? e0 : 0.2f * e0;
        float p0 = __expf(e0);
        ssum += p0;
        float2 f00 = __half22float2(*(__half2*)&u0.x);
        float2 f01 = __half22float2(*(__half2*)&u0.y);
        acc.x += p0 * f00.x; acc.y += p0 * f00.y;
        acc.z += p0 * f01.x; acc.w += p0 * f01.y;
    }

    float inv = 1.f / ssum;
    float4 bv = *(const float4*)(bias + lane * 4);
    float4 o;
    o.x = acc.x * inv + bv.x;
    o.y = acc.y * inv + bv.y;
    o.z = acc.z * inv + bv.z;
    o.w = acc.w * inv + bv.w;
    if (relu_res) {
        float4 r = *(const float4*)(xin + (size_t)n * D + lane * 4);
        o.x = fmaxf(o.x + r.x, 0.f);
        o.y = fmaxf(o.y + r.y, 0.f);
        o.z = fmaxf(o.z + r.z, 0.f);
        o.w = fmaxf(o.w + r.w, 0.f);
    }
    *(float4*)(outp + (size_t)n * D + lane * 4) = o;
}

// ---------------- launch (9 kernels) ----------------
extern "C" void kernel_launch(void* const* d_in, const int* in_sizes, int n_in,
                              void* d_out, int out_size) {
    const float* x   = (const float*)d_in[0];
    const int*   ei  = (const int*)  d_in[1];
    const float* w0  = (const float*)d_in[2];
    const float* b0  = (const float*)d_in[3];
    const float* w1  = (const float*)d_in[4];
    const float* as1 = (const float*)d_in[5];
    const float* ad1 = (const float*)d_in[6];
    const float* b1  = (const float*)d_in[7];
    const float* w2  = (const float*)d_in[8];
    const float* as2 = (const float*)d_in[9];
    const float* ad2 = (const float*)d_in[10];
    const float* b2  = (const float*)d_in[11];
    const float* w3  = (const float*)d_in[12];
    const float* as3 = (const float*)d_in[13];
    const float* ad3 = (const float*)d_in[14];
    const float* b3  = (const float*)d_in[15];
    float* out = (float*)d_out;

    int wgrid = (N_NODES * 32) / 256;       // 6250 blocks, 1 warp per node

    // L0: gemm0 (x@w0+b0 -> g_h)  ∥  edge-count histogram
    k_fused0<<<GGRID + CNT_BLK, 256>>>(x, w0, b0, ei);
    // L1: gemm1 (g_h@w1 -> xph/als/ald)  ∥  scan1 (block-local prefix of deg+1)
    k_fused1<<<GGRID + NB, 256>>>(w1, as1, ad1);
    // L2/L3: finish CSR
    k_scan3<<<(N_NODES + 255) / 256, 256>>>();
    k_scatter<<<(N_NODES + N_EDGES + 255) / 256, 256>>>(ei);
    // layer 1 aggregate: g_h residual -> g_h2
    k_agg<<<wgrid, 256>>>(0, nullptr, 1, b1, 1);
    // layer 2
    k_gemm_tc<<<GGRID, 256>>>(nullptr, 1, w2, nullptr, 0, as2, ad2);
    k_agg<<<wgrid, 256>>>(1, nullptr, 0, b2, 1);
    // layer 3
    k_gemm_tc<<<GGRID, 256>>>(nullptr, 0, w3, nullptr, 0, as3, ad3);
    k_agg<<<wgrid, 256>>>(0, out, 0, b3, 0);
}